// round 13
// baseline (speedup 1.0000x reference)
#include <cuda_runtime.h>
#include <cuda_bf16.h>
#include <math.h>
#include <stdint.h>

// Problem constants
#define DDIM 1024
#define TDIM 2048
#define BDIM 32
#define MTOT 65536
#define WSTRIDE 2048        // W row stride in floats (2*D)

// GEMM tiling (bf16)
#define BM 128
#define BN 128
#define BK 64               // bf16 k-elements per stage
#define NTILES 8            // 1024 / BN
#define KT 16               // 1024 / BK
#define STAGES 3

#define STAGEB 18432u       // bytes per stage per matrix: 128 rows * 144B
#define SMEM_PART 110592u   // partial[] offset (after 3*(A+B) stages)
#define SMEM_TOTAL 112640u

// Scratch (static __device__ arrays: allocation-free)
__device__ __nv_bfloat16 g_w2b[(size_t)DDIM * DDIM];
__device__ float g_qh[BDIM * DDIM];
__device__ float g_part[(size_t)NTILES * MTOT];

// ---------------------------------------------------------------------------
__device__ __forceinline__ void mma_bf16(float* d, const uint32_t* a, uint32_t b0, uint32_t b1) {
    asm volatile(
        "mma.sync.aligned.m16n8k16.row.col.f32.bf16.bf16.f32 "
        "{%0,%1,%2,%3}, {%4,%5,%6,%7}, {%8,%9}, {%0,%1,%2,%3};"
        : "+f"(d[0]), "+f"(d[1]), "+f"(d[2]), "+f"(d[3])
        : "r"(a[0]), "r"(a[1]), "r"(a[2]), "r"(a[3]), "r"(b0), "r"(b1));
}
__device__ __forceinline__ void cp16(uint32_t dst, const void* src) {
    asm volatile("cp.async.cg.shared.global [%0], [%1], 16;" :: "r"(dst), "l"(src));
}
#define LDSM4(r0, r1, r2, r3, addr) \
    asm volatile("ldmatrix.sync.aligned.m8n8.x4.shared.b16 {%0,%1,%2,%3}, [%4];" \
        : "=r"(r0), "=r"(r1), "=r"(r2), "=r"(r3) : "r"(addr))

__device__ __forceinline__ uint32_t cvt2(float hi, float lo) {
    uint32_t r;
    asm("cvt.rn.bf16x2.f32 %0, %1, %2;" : "=r"(r) : "f"(hi), "f"(lo));
    return r;
}
__device__ __forceinline__ uint32_t smem_u32(const void* p) {
    uint32_t a;
    asm("{ .reg .u64 t; cvta.to.shared.u64 t, %1; cvt.u32.u64 %0, t; }" : "=r"(a) : "l"(p));
    return a;
}

// ---------------------------------------------------------------------------
// Convert W2 = W[:, 1024:2048] -> g_w2b (bf16). Standard layout (no permutation).
__global__ __launch_bounds__(256) void conv_w2(const float* __restrict__ W)
{
    const int n = blockIdx.x;
    const int t = threadIdx.x;
    const float4 x = *(const float4*)(W + (size_t)n * WSTRIDE + DDIM + t * 4);
    __nv_bfloat162 p0 = __floats2bfloat162_rn(x.x, x.y);
    __nv_bfloat162 p1 = __floats2bfloat162_rn(x.z, x.w);
    uint2 o;
    o.x = *(uint32_t*)&p0;
    o.y = *(uint32_t*)&p1;
    ((uint2*)(g_w2b + (size_t)n * DDIM))[t] = o;
}

// ---------------------------------------------------------------------------
// qh[b,d] = W1[d,:] . hidden[b,:] + bias[d]   (proven R10 version)
__global__ __launch_bounds__(256) void qh_kernel(
    const float* __restrict__ hidden, const float* __restrict__ W,
    const float* __restrict__ bias)
{
    const int b = blockIdx.y;
    const int warp = threadIdx.x >> 5;
    const int lane = threadIdx.x & 31;
    const int d = blockIdx.x * 8 + warp;

    const float* wr = W + (size_t)d * WSTRIDE;
    const float* h  = hidden + (size_t)b * DDIM;

    float acc = 0.f;
    #pragma unroll 8
    for (int k = lane; k < DDIM; k += 32) acc += wr[k] * h[k];
    #pragma unroll
    for (int o = 16; o > 0; o >>= 1) acc += __shfl_xor_sync(0xFFFFFFFFu, acc, o);
    if (lane == 0) g_qh[(size_t)b * DDIM + d] = acc + bias[d];
}

// ---------------------------------------------------------------------------
// bf16 GEMM with fused A conversion (f32 gmem -> LDG -> cvt -> bf16 STS).
// smem layout / LDSM / fragments / COMP are byte-identical to the R10 champion;
// only the A fill path changed (was cp.async from pre-converted g_encb).
// 128x128 tile, 512 threads (16 warps, 32x32 warp tiles), 3-stage pipeline,
// fragment ping-pong.
__global__ __launch_bounds__(512, 1) void bf_gemm(
    const float* __restrict__ A, const float* __restrict__ v)
{
    extern __shared__ char smem[];
    const uint32_t uAs = smem_u32(smem);              // A stages (bf16)
    const uint32_t uBs = uAs + STAGES * STAGEB;       // B stages (bf16)

    const int tid  = threadIdx.x;
    const int lane = tid & 31;
    const int warp = tid >> 5;
    const int wm   = warp >> 2;     // 0..3 (M, 32 rows)
    const int wn   = warp & 3;      // 0..3 (N, 32 cols)
    const int gid  = lane >> 2;
    const int tig  = lane & 3;

    const int nx   = blockIdx.x;
    const int m0   = blockIdx.y * BM;
    const int n0   = nx * BN;
    const int bidx = m0 >> 11;

    float acc[2][4][4];
    #pragma unroll
    for (int i = 0; i < 2; i++)
        #pragma unroll
        for (int j = 0; j < 4; j++)
            #pragma unroll
            for (int k = 0; k < 4; k++) acc[i][j][k] = 0.f;

    // Fill mapping (both A and B): rows {r0, r0+64}, 16B bf16 chunk c8.
    const int r0 = tid >> 3;            // 0..63
    const int c8 = tid & 7;             // 0..7
    const uint32_t aoff = (uint32_t)r0 * 144u + (uint32_t)c8 * 16u;  // within stage
    const uint32_t dB = uBs + aoff;
    const __nv_bfloat16* pB = g_w2b + (size_t)(n0 + r0) * DDIM + c8 * 8;
    // A gmem: f32, 8 floats per (row, chunk)
    const float* pA0 = A + (size_t)(m0 + r0) * DDIM + c8 * 8;

    #define ISSUE_B(c, s)                                                        \
    do {                                                                         \
        const uint32_t _so = (uint32_t)(s) * STAGEB;                             \
        const __nv_bfloat16* _gb = pB + (size_t)(c) * BK;                        \
        cp16(dB + _so,         _gb);                                             \
        cp16(dB + _so + 9216u, _gb + (size_t)64 * DDIM);                         \
        asm volatile("cp.async.commit_group;");                                  \
    } while (0)

    float4 av0, av1, av2, av3;          // A pipeline registers (16 f32)

    #define LDGA(c)                                                              \
    do {                                                                         \
        const float* _ga = pA0 + (size_t)(c) * BK;                               \
        av0 = *(const float4*)(_ga);                                             \
        av1 = *(const float4*)(_ga + 4);                                         \
        av2 = *(const float4*)(_ga + (size_t)64 * DDIM);                         \
        av3 = *(const float4*)(_ga + (size_t)64 * DDIM + 4);                     \
    } while (0)

    #define STSA(s)                                                              \
    do {                                                                         \
        const uint32_t _so = (uint32_t)(s) * STAGEB;                             \
        uint4 _u0 = make_uint4(cvt2(av0.y, av0.x), cvt2(av0.w, av0.z),           \
                               cvt2(av1.y, av1.x), cvt2(av1.w, av1.z));          \
        uint4 _u1 = make_uint4(cvt2(av2.y, av2.x), cvt2(av2.w, av2.z),           \
                               cvt2(av3.y, av3.x), cvt2(av3.w, av3.z));          \
        *(uint4*)(smem + _so + aoff)         = _u0;                              \
        *(uint4*)(smem + _so + aoff + 9216u) = _u1;                              \
    } while (0)

    // ldmatrix base addresses (lane-dependent) — identical to R10
    const uint32_t aBase = uAs + (uint32_t)(wm * 32 + (lane & 15)) * 144 + (uint32_t)(lane >> 4) * 16;
    const uint32_t bBase = uBs + (uint32_t)(wn * 32 + (lane & 15)) * 144 + (uint32_t)(lane >> 4) * 16;

    uint32_t fa[2][2][4];
    uint32_t fb[2][2][4];

    #define LOADF(s, ks, p)                                                      \
    do {                                                                         \
        const uint32_t _o = (uint32_t)(s) * STAGEB + (uint32_t)(ks) * 32u;       \
        _Pragma("unroll")                                                        \
        for (int q = 0; q < 2; q++)                                              \
            LDSM4(fb[p][q][0], fb[p][q][1], fb[p][q][2], fb[p][q][3],            \
                  bBase + _o + (uint32_t)q * 2304u);                             \
        _Pragma("unroll")                                                        \
        for (int mi = 0; mi < 2; mi++)                                           \
            LDSM4(fa[p][mi][0], fa[p][mi][1], fa[p][mi][2], fa[p][mi][3],        \
                  aBase + _o + (uint32_t)mi * 2304u);                            \
    } while (0)

    #define COMP(p)                                                              \
    do {                                                                         \
        _Pragma("unroll")                                                        \
        for (int mi = 0; mi < 2; mi++)                                           \
            _Pragma("unroll")                                                    \
            for (int ni = 0; ni < 4; ni++)                                       \
                mma_bf16(acc[mi][ni], fa[p][mi],                                 \
                         fb[p][ni >> 1][ni & 1], fb[p][ni >> 1][2 + (ni & 1)]);  \
    } while (0)

    // Prologue: B via cp.async (stages 0,1); A via LDG/cvt/STS (stages 0,1).
    ISSUE_B(0, 0);
    ISSUE_B(1, 1);
    LDGA(0); STSA(0);
    LDGA(1); STSA(1);
    asm volatile("cp.async.wait_group 1;");   // B stage 0 resident
    __syncthreads();                           // A STS visible
    LOADF(0, 0, 0);

    for (int kt = 0; kt < KT; kt++) {
        const int s = kt % STAGES;
        LOADF(s, 1, 1); COMP(0);                       // ks0
        if (kt + 2 < KT) {
            LDGA(kt + 2);                              // ~1000cyc before STSA
            ISSUE_B(kt + 2, (kt + 2) % STAGES);
        }
        LOADF(s, 2, 0); COMP(1);                       // ks1
        LOADF(s, 3, 1); COMP(0);                       // ks2
        if (kt + 2 < KT) STSA((kt + 2) % STAGES);      // stage consumed at kt+2
        if (kt + 1 < KT) {
            if (kt + 2 < KT) asm volatile("cp.async.wait_group 1;");
            else             asm volatile("cp.async.wait_group 0;");
            __syncthreads();
            LOADF((kt + 1) % STAGES, 0, 0);            // next ks0, shadowed by COMP below
        }
        COMP(1);                                       // ks3
    }

    // Epilogue: relu(acc + qh) * v, reduced over this CTA's 128 d-columns.
    float* partial = (float*)(smem + SMEM_PART);   // [4][128]
    float pr[2][2];
    #pragma unroll
    for (int mi = 0; mi < 2; mi++) { pr[mi][0] = 0.f; pr[mi][1] = 0.f; }

    #pragma unroll
    for (int ni = 0; ni < 4; ni++) {
        const int c = n0 + wn * 32 + ni * 8 + tig * 2;
        const float q0 = g_qh[(size_t)bidx * DDIM + c];
        const float q1 = g_qh[(size_t)bidx * DDIM + c + 1];
        const float v0 = v[c];
        const float v1 = v[c + 1];
        #pragma unroll
        for (int mi = 0; mi < 2; mi++) {
            pr[mi][0] += fmaxf(acc[mi][ni][0] + q0, 0.f) * v0;
            pr[mi][0] += fmaxf(acc[mi][ni][1] + q1, 0.f) * v1;
            pr[mi][1] += fmaxf(acc[mi][ni][2] + q0, 0.f) * v0;
            pr[mi][1] += fmaxf(acc[mi][ni][3] + q1, 0.f) * v1;
        }
    }

    __syncthreads();
    #pragma unroll
    for (int mi = 0; mi < 2; mi++)
        #pragma unroll
        for (int j = 0; j < 2; j++) {
            float p = pr[mi][j];
            p += __shfl_xor_sync(0xFFFFFFFFu, p, 1);
            p += __shfl_xor_sync(0xFFFFFFFFu, p, 2);
            if (tig == 0) partial[wn * BM + wm * 32 + mi * 16 + j * 8 + gid] = p;
        }
    __syncthreads();

    if (tid < BM) {
        const float s = partial[0 * BM + tid] + partial[1 * BM + tid] +
                        partial[2 * BM + tid] + partial[3 * BM + tid];
        g_part[(size_t)nx * MTOT + m0 + tid] = s;
    }
}

// ---------------------------------------------------------------------------
// Sum 8 N-strip partials -> scores, softmax over T. 1024 threads (2 t each).
__global__ __launch_bounds__(1024) void softmax_kernel(float* __restrict__ out)
{
    const int b = blockIdx.x;
    const int tid = threadIdx.x;
    __shared__ float red[1024];

    float vals[2];
    #pragma unroll
    for (int j = 0; j < 2; j++) {
        const int t = tid + j * 1024;
        float s = 0.f;
        #pragma unroll
        for (int nxi = 0; nxi < NTILES; nxi++)
            s += g_part[(size_t)nxi * MTOT + (size_t)b * TDIM + t];
        vals[j] = s;
    }
    float mx = fmaxf(vals[0], vals[1]);

    red[tid] = mx;
    __syncthreads();
    #pragma unroll
    for (int o = 512; o > 0; o >>= 1) {
        if (tid < o) red[tid] = fmaxf(red[tid], red[tid + o]);
        __syncthreads();
    }
    const float m = red[0];
    __syncthreads();

    float sum = 0.f;
    #pragma unroll
    for (int j = 0; j < 2; j++) {
        vals[j] = expf(vals[j] - m);
        sum += vals[j];
    }
    red[tid] = sum;
    __syncthreads();
    #pragma unroll
    for (int o = 512; o > 0; o >>= 1) {
        if (tid < o) red[tid] += red[tid + o];
        __syncthreads();
    }
    const float inv = 1.f / red[0];

    #pragma unroll
    for (int j = 0; j < 2; j++)
        out[(size_t)b * TDIM + tid + j * 1024] = vals[j] * inv;
}

// ---------------------------------------------------------------------------
extern "C" void kernel_launch(void* const* d_in, const int* in_sizes, int n_in,
                              void* d_out, int out_size)
{
    const float* hidden = (const float*)d_in[0];
    const float* enc    = (const float*)d_in[1];
    const float* W      = (const float*)d_in[2];
    const float* bias   = (const float*)d_in[3];
    const float* v      = (const float*)d_in[4];
    float* out = (float*)d_out;

    cudaFuncSetAttribute(bf_gemm, cudaFuncAttributeMaxDynamicSharedMemorySize, SMEM_TOTAL);

    conv_w2<<<DDIM, 256>>>(W);
    qh_kernel<<<dim3(DDIM / 8, BDIM), 256>>>(hidden, W, bias);
    bf_gemm<<<dim3(NTILES, MTOT / BM), 512, SMEM_TOTAL>>>(enc, v);
    softmax_kernel<<<BDIM, 1024>>>(out);
}

// round 14
// speedup vs baseline: 1.2067x; 1.2067x over previous
#include <cuda_runtime.h>
#include <cuda_bf16.h>
#include <math.h>
#include <stdint.h>

// Problem constants
#define DDIM 1024
#define TDIM 2048
#define BDIM 32
#define MTOT 65536
#define WSTRIDE 2048        // W row stride in floats (2*D)

// GEMM tiling (bf16): 128x64 CTA tile, 2 CTAs/SM for barrier decoupling
#define BM 128
#define BN 64
#define BK 64               // bf16 k-elements per stage
#define NTILES 16           // 1024 / BN
#define KT 16               // 1024 / BK
#define STAGES 3

#define STAGEB_A 18432u     // 128 rows * 144B
#define STAGEB_B 9216u      // 64 rows * 144B
#define SMEM_PART 82944u    // 3*(A+B)
#define SMEM_TOTAL 83968u   // + partial[2][128] floats

// Scratch (static __device__ arrays: allocation-free)
__device__ __nv_bfloat16 g_encb[(size_t)MTOT * DDIM];
__device__ __nv_bfloat16 g_w2b[(size_t)DDIM * DDIM];
__device__ float g_qh[BDIM * DDIM];
__device__ float g_part[(size_t)NTILES * MTOT];

// ---------------------------------------------------------------------------
__device__ __forceinline__ void mma_bf16(float* d, const uint32_t* a, uint32_t b0, uint32_t b1) {
    asm volatile(
        "mma.sync.aligned.m16n8k16.row.col.f32.bf16.bf16.f32 "
        "{%0,%1,%2,%3}, {%4,%5,%6,%7}, {%8,%9}, {%0,%1,%2,%3};"
        : "+f"(d[0]), "+f"(d[1]), "+f"(d[2]), "+f"(d[3])
        : "r"(a[0]), "r"(a[1]), "r"(a[2]), "r"(a[3]), "r"(b0), "r"(b1));
}
__device__ __forceinline__ void cp16(uint32_t dst, const void* src) {
    asm volatile("cp.async.cg.shared.global [%0], [%1], 16;" :: "r"(dst), "l"(src));
}
#define LDSM4(r0, r1, r2, r3, addr) \
    asm volatile("ldmatrix.sync.aligned.m8n8.x4.shared.b16 {%0,%1,%2,%3}, [%4];" \
        : "=r"(r0), "=r"(r1), "=r"(r2), "=r"(r3) : "r"(addr))

__device__ __forceinline__ uint32_t smem_u32(const void* p) {
    uint32_t a;
    asm("{ .reg .u64 t; cvta.to.shared.u64 t, %1; cvt.u32.u64 %0, t; }" : "=r"(a) : "l"(p));
    return a;
}

// ---------------------------------------------------------------------------
// Convert enc (f32) -> g_encb (bf16). One float4 per thread.
__global__ __launch_bounds__(256) void conv_enc(const float4* __restrict__ src)
{
    const size_t i = (size_t)blockIdx.x * 256 + threadIdx.x;
    const float4 x = src[i];
    __nv_bfloat162 p0 = __floats2bfloat162_rn(x.x, x.y);
    __nv_bfloat162 p1 = __floats2bfloat162_rn(x.z, x.w);
    uint2 o;
    o.x = *(uint32_t*)&p0;
    o.y = *(uint32_t*)&p1;
    ((uint2*)g_encb)[i] = o;
}

// Convert W2 = W[:, 1024:2048] -> g_w2b (bf16).
__global__ __launch_bounds__(256) void conv_w2(const float* __restrict__ W)
{
    const int n = blockIdx.x;
    const int t = threadIdx.x;
    const float4 x = *(const float4*)(W + (size_t)n * WSTRIDE + DDIM + t * 4);
    __nv_bfloat162 p0 = __floats2bfloat162_rn(x.x, x.y);
    __nv_bfloat162 p1 = __floats2bfloat162_rn(x.z, x.w);
    uint2 o;
    o.x = *(uint32_t*)&p0;
    o.y = *(uint32_t*)&p1;
    ((uint2*)(g_w2b + (size_t)n * DDIM))[t] = o;
}

// ---------------------------------------------------------------------------
// qh[b,d] = W1[d,:] . hidden[b,:] + bias[d]   (proven R10 version)
__global__ __launch_bounds__(256) void qh_kernel(
    const float* __restrict__ hidden, const float* __restrict__ W,
    const float* __restrict__ bias)
{
    const int b = blockIdx.y;
    const int warp = threadIdx.x >> 5;
    const int lane = threadIdx.x & 31;
    const int d = blockIdx.x * 8 + warp;

    const float* wr = W + (size_t)d * WSTRIDE;
    const float* h  = hidden + (size_t)b * DDIM;

    float acc = 0.f;
    #pragma unroll 8
    for (int k = lane; k < DDIM; k += 32) acc += wr[k] * h[k];
    #pragma unroll
    for (int o = 16; o > 0; o >>= 1) acc += __shfl_xor_sync(0xFFFFFFFFu, acc, o);
    if (lane == 0) g_qh[(size_t)b * DDIM + d] = acc + bias[d];
}

// ---------------------------------------------------------------------------
// bf16 GEMM: 128x64 CTA tile, 256 threads (8 warps, 32x32 warp tiles),
// 2 CTAs/SM (decoupled barriers), 3-stage cp.async pipeline, fragment
// ping-pong. Same warp-tile machinery as the R10 champion.
__global__ __launch_bounds__(256, 2) void bf_gemm(const float* __restrict__ v)
{
    extern __shared__ char smem[];
    const uint32_t uAs = smem_u32(smem);              // A stages
    const uint32_t uBs = uAs + STAGES * STAGEB_A;     // B stages

    const int tid  = threadIdx.x;
    const int lane = tid & 31;
    const int warp = tid >> 5;
    const int wm   = warp >> 1;     // 0..3 (M, 32 rows)
    const int wn   = warp & 1;      // 0..1 (N, 32 cols)
    const int gid  = lane >> 2;
    const int tig  = lane & 3;

    const int nx   = blockIdx.x;
    const int m0   = blockIdx.y * BM;
    const int n0   = nx * BN;
    const int bidx = m0 >> 11;

    float acc[2][4][4];
    #pragma unroll
    for (int i = 0; i < 2; i++)
        #pragma unroll
        for (int j = 0; j < 4; j++)
            #pragma unroll
            for (int k = 0; k < 4; k++) acc[i][j][k] = 0.f;

    // cp.async mapping (256 threads):
    //   A: 128 rows x 8 chunks = 1024 ops -> rows {ra+32j}, j=0..3
    //   B:  64 rows x 8 chunks =  512 ops -> rows {rb, rb+32}
    const int ra = tid >> 3;            // 0..31
    const int c8 = tid & 7;             // 0..7
    const uint32_t dA = uAs + (uint32_t)ra * 144 + (uint32_t)c8 * 16;
    const uint32_t dB = uBs + (uint32_t)ra * 144 + (uint32_t)c8 * 16;
    const __nv_bfloat16* pA = g_encb + (size_t)(m0 + ra) * DDIM + c8 * 8;
    const __nv_bfloat16* pB = g_w2b  + (size_t)(n0 + ra) * DDIM + c8 * 8;

    #define ISSUE_TILE(c, s)                                                     \
    do {                                                                         \
        const uint32_t _sa = (uint32_t)(s) * STAGEB_A;                           \
        const uint32_t _sb = (uint32_t)(s) * STAGEB_B;                           \
        const __nv_bfloat16* _ga = pA + (size_t)(c) * BK;                        \
        const __nv_bfloat16* _gb = pB + (size_t)(c) * BK;                        \
        _Pragma("unroll")                                                        \
        for (int j = 0; j < 4; j++)                                              \
            cp16(dA + _sa + (uint32_t)j * 4608u, _ga + (size_t)j * 32 * DDIM);   \
        cp16(dB + _sb,          _gb);                                            \
        cp16(dB + _sb + 4608u,  _gb + (size_t)32 * DDIM);                        \
        asm volatile("cp.async.commit_group;");                                  \
    } while (0)

    // ldmatrix base addresses (lane-dependent)
    const uint32_t aBase = uAs + (uint32_t)(wm * 32 + (lane & 15)) * 144 + (uint32_t)(lane >> 4) * 16;
    const uint32_t bBase = uBs + (uint32_t)(wn * 32 + (lane & 15)) * 144 + (uint32_t)(lane >> 4) * 16;

    uint32_t fa[2][2][4];
    uint32_t fb[2][2][4];

    // B issued first (extra latency cover before the first mma of COMP).
    #define LOADF(s, ks, p)                                                      \
    do {                                                                         \
        const uint32_t _ob = (uint32_t)(s) * STAGEB_B + (uint32_t)(ks) * 32u;    \
        _Pragma("unroll")                                                        \
        for (int q = 0; q < 2; q++)                                              \
            LDSM4(fb[p][q][0], fb[p][q][1], fb[p][q][2], fb[p][q][3],            \
                  bBase + _ob + (uint32_t)q * 2304u);                            \
        const uint32_t _oa = (uint32_t)(s) * STAGEB_A + (uint32_t)(ks) * 32u;    \
        _Pragma("unroll")                                                        \
        for (int mi = 0; mi < 2; mi++)                                           \
            LDSM4(fa[p][mi][0], fa[p][mi][1], fa[p][mi][2], fa[p][mi][3],        \
                  aBase + _oa + (uint32_t)mi * 2304u);                           \
    } while (0)

    // fb x4 pair q covers ni=2q (regs 0,2) and ni=2q+1 (regs 1,3)
    #define COMP(p)                                                              \
    do {                                                                         \
        _Pragma("unroll")                                                        \
        for (int mi = 0; mi < 2; mi++)                                           \
            _Pragma("unroll")                                                    \
            for (int ni = 0; ni < 4; ni++)                                       \
                mma_bf16(acc[mi][ni], fa[p][mi],                                 \
                         fb[p][ni >> 1][ni & 1], fb[p][ni >> 1][2 + (ni & 1)]);  \
    } while (0)

    // Prologue: fill stages 0 and 1; stage 0 resident before first frag load.
    ISSUE_TILE(0, 0);
    ISSUE_TILE(1, 1);
    asm volatile("cp.async.wait_group 1;");
    __syncthreads();
    LOADF(0, 0, 0);

    for (int kt = 0; kt < KT; kt++) {
        const int s = kt % STAGES;
        LOADF(s, 1, 1); COMP(0);                       // ks0
        if (kt + 2 < KT) ISSUE_TILE(kt + 2, (kt + 2) % STAGES);
        LOADF(s, 2, 0); COMP(1);                       // ks1
        LOADF(s, 3, 1); COMP(0);                       // ks2
        if (kt + 1 < KT) {
            if (kt + 2 < KT) asm volatile("cp.async.wait_group 1;");
            else             asm volatile("cp.async.wait_group 0;");
            __syncthreads();
            LOADF((kt + 1) % STAGES, 0, 0);            // next ks0, shadowed by COMP below
        }
        COMP(1);                                       // ks3
    }

    // Epilogue: relu(acc + qh) * v, reduced over this CTA's 64 d-columns.
    float* partial = (float*)(smem + SMEM_PART);   // [2][128]
    float pr[2][2];
    #pragma unroll
    for (int mi = 0; mi < 2; mi++) { pr[mi][0] = 0.f; pr[mi][1] = 0.f; }

    #pragma unroll
    for (int ni = 0; ni < 4; ni++) {
        const int c = n0 + wn * 32 + ni * 8 + tig * 2;
        const float q0 = g_qh[(size_t)bidx * DDIM + c];
        const float q1 = g_qh[(size_t)bidx * DDIM + c + 1];
        const float v0 = v[c];
        const float v1 = v[c + 1];
        #pragma unroll
        for (int mi = 0; mi < 2; mi++) {
            pr[mi][0] += fmaxf(acc[mi][ni][0] + q0, 0.f) * v0;
            pr[mi][0] += fmaxf(acc[mi][ni][1] + q1, 0.f) * v1;
            pr[mi][1] += fmaxf(acc[mi][ni][2] + q0, 0.f) * v0;
            pr[mi][1] += fmaxf(acc[mi][ni][3] + q1, 0.f) * v1;
        }
    }

    __syncthreads();
    #pragma unroll
    for (int mi = 0; mi < 2; mi++)
        #pragma unroll
        for (int j = 0; j < 2; j++) {
            float p = pr[mi][j];
            p += __shfl_xor_sync(0xFFFFFFFFu, p, 1);
            p += __shfl_xor_sync(0xFFFFFFFFu, p, 2);
            if (tig == 0) partial[wn * BM + wm * 32 + mi * 16 + j * 8 + gid] = p;
        }
    __syncthreads();

    if (tid < BM) {
        const float s = partial[tid] + partial[BM + tid];
        g_part[(size_t)nx * MTOT + m0 + tid] = s;
    }
}

// ---------------------------------------------------------------------------
// Sum 16 N-strip partials -> scores, softmax over T. 1024 threads (2 t each).
__global__ __launch_bounds__(1024) void softmax_kernel(float* __restrict__ out)
{
    const int b = blockIdx.x;
    const int tid = threadIdx.x;
    __shared__ float red[1024];

    float vals[2];
    #pragma unroll
    for (int j = 0; j < 2; j++) {
        const int t = tid + j * 1024;
        float s = 0.f;
        #pragma unroll
        for (int nxi = 0; nxi < NTILES; nxi++)
            s += g_part[(size_t)nxi * MTOT + (size_t)b * TDIM + t];
        vals[j] = s;
    }
    float mx = fmaxf(vals[0], vals[1]);

    red[tid] = mx;
    __syncthreads();
    #pragma unroll
    for (int o = 512; o > 0; o >>= 1) {
        if (tid < o) red[tid] = fmaxf(red[tid], red[tid + o]);
        __syncthreads();
    }
    const float m = red[0];
    __syncthreads();

    float sum = 0.f;
    #pragma unroll
    for (int j = 0; j < 2; j++) {
        vals[j] = expf(vals[j] - m);
        sum += vals[j];
    }
    red[tid] = sum;
    __syncthreads();
    #pragma unroll
    for (int o = 512; o > 0; o >>= 1) {
        if (tid < o) red[tid] += red[tid + o];
        __syncthreads();
    }
    const float inv = 1.f / red[0];

    #pragma unroll
    for (int j = 0; j < 2; j++)
        out[(size_t)b * TDIM + tid + j * 1024] = vals[j] * inv;
}

// ---------------------------------------------------------------------------
extern "C" void kernel_launch(void* const* d_in, const int* in_sizes, int n_in,
                              void* d_out, int out_size)
{
    const float* hidden = (const float*)d_in[0];
    const float* enc    = (const float*)d_in[1];
    const float* W      = (const float*)d_in[2];
    const float* bias   = (const float*)d_in[3];
    const float* v      = (const float*)d_in[4];
    float* out = (float*)d_out;

    cudaFuncSetAttribute(bf_gemm, cudaFuncAttributeMaxDynamicSharedMemorySize, SMEM_TOTAL);

    conv_enc<<<65536, 256>>>((const float4*)enc);
    conv_w2<<<DDIM, 256>>>(W);
    qh_kernel<<<dim3(DDIM / 8, BDIM), 256>>>(hidden, W, bias);
    bf_gemm<<<dim3(NTILES, MTOT / BM), 256, SMEM_TOTAL>>>(v);
    softmax_kernel<<<BDIM, 1024>>>(out);
}

// round 15
// speedup vs baseline: 1.3439x; 1.1137x over previous
#include <cuda_runtime.h>
#include <cuda_bf16.h>
#include <math.h>
#include <stdint.h>

// Problem constants
#define DDIM 1024
#define TDIM 2048
#define BDIM 32
#define MTOT 65536
#define WSTRIDE 2048        // W row stride in floats (2*D)

// GEMM tiling (bf16): 128x128 CTA tile, 8 warps of 32x64 warp tiles, 2 CTAs/SM
#define BM 128
#define BN 128
#define BK 64               // bf16 k-elements per stage
#define NTILES 8            // 1024 / BN
#define KT 16               // 1024 / BK
#define STAGES 3

#define STAGEB 18432u       // bytes per stage per matrix: 128 rows * 144B
#define SMEM_PART 110592u   // after 3*(A+B) stages
#define SMEM_TOTAL 111616u  // + partial[2][128] floats

// Scratch (static __device__ arrays: allocation-free)
__device__ __nv_bfloat16 g_encb[(size_t)MTOT * DDIM];
__device__ __nv_bfloat16 g_w2b[(size_t)DDIM * DDIM];
__device__ float g_qh[BDIM * DDIM];
__device__ float g_part[(size_t)NTILES * MTOT];

// ---------------------------------------------------------------------------
__device__ __forceinline__ void mma_bf16(float* d, const uint32_t* a, uint32_t b0, uint32_t b1) {
    asm volatile(
        "mma.sync.aligned.m16n8k16.row.col.f32.bf16.bf16.f32 "
        "{%0,%1,%2,%3}, {%4,%5,%6,%7}, {%8,%9}, {%0,%1,%2,%3};"
        : "+f"(d[0]), "+f"(d[1]), "+f"(d[2]), "+f"(d[3])
        : "r"(a[0]), "r"(a[1]), "r"(a[2]), "r"(a[3]), "r"(b0), "r"(b1));
}
__device__ __forceinline__ void cp16(uint32_t dst, const void* src) {
    asm volatile("cp.async.cg.shared.global [%0], [%1], 16;" :: "r"(dst), "l"(src));
}
#define LDSM4(r0, r1, r2, r3, addr) \
    asm volatile("ldmatrix.sync.aligned.m8n8.x4.shared.b16 {%0,%1,%2,%3}, [%4];" \
        : "=r"(r0), "=r"(r1), "=r"(r2), "=r"(r3) : "r"(addr))

__device__ __forceinline__ uint32_t smem_u32(const void* p) {
    uint32_t a;
    asm("{ .reg .u64 t; cvta.to.shared.u64 t, %1; cvt.u32.u64 %0, t; }" : "=r"(a) : "l"(p));
    return a;
}

// ---------------------------------------------------------------------------
// Convert enc (f32) -> g_encb (bf16). One float4 per thread.
__global__ __launch_bounds__(256) void conv_enc(const float4* __restrict__ src)
{
    const size_t i = (size_t)blockIdx.x * 256 + threadIdx.x;
    const float4 x = src[i];
    __nv_bfloat162 p0 = __floats2bfloat162_rn(x.x, x.y);
    __nv_bfloat162 p1 = __floats2bfloat162_rn(x.z, x.w);
    uint2 o;
    o.x = *(uint32_t*)&p0;
    o.y = *(uint32_t*)&p1;
    ((uint2*)g_encb)[i] = o;
}

// Convert W2 = W[:, 1024:2048] -> g_w2b (bf16).
__global__ __launch_bounds__(256) void conv_w2(const float* __restrict__ W)
{
    const int n = blockIdx.x;
    const int t = threadIdx.x;
    const float4 x = *(const float4*)(W + (size_t)n * WSTRIDE + DDIM + t * 4);
    __nv_bfloat162 p0 = __floats2bfloat162_rn(x.x, x.y);
    __nv_bfloat162 p1 = __floats2bfloat162_rn(x.z, x.w);
    uint2 o;
    o.x = *(uint32_t*)&p0;
    o.y = *(uint32_t*)&p1;
    ((uint2*)(g_w2b + (size_t)n * DDIM))[t] = o;
}

// ---------------------------------------------------------------------------
// qh[b,d] = W1[d,:] . hidden[b,:] + bias[d]   (proven R10 version)
__global__ __launch_bounds__(256) void qh_kernel(
    const float* __restrict__ hidden, const float* __restrict__ W,
    const float* __restrict__ bias)
{
    const int b = blockIdx.y;
    const int warp = threadIdx.x >> 5;
    const int lane = threadIdx.x & 31;
    const int d = blockIdx.x * 8 + warp;

    const float* wr = W + (size_t)d * WSTRIDE;
    const float* h  = hidden + (size_t)b * DDIM;

    float acc = 0.f;
    #pragma unroll 8
    for (int k = lane; k < DDIM; k += 32) acc += wr[k] * h[k];
    #pragma unroll
    for (int o = 16; o > 0; o >>= 1) acc += __shfl_xor_sync(0xFFFFFFFFu, acc, o);
    if (lane == 0) g_qh[(size_t)b * DDIM + d] = acc + bias[d];
}

// ---------------------------------------------------------------------------
// bf16 GEMM: 128x128 CTA tile, 256 threads (8 warps, 32x64 warp tiles: fewer
// fragment bytes per MAC -> lower smem-crossbar load), 2 CTAs/SM, 3-stage
// cp.async pipeline, single-buffered fragments (TLP covers LDSM latency).
__global__ __launch_bounds__(256, 2) void bf_gemm(const float* __restrict__ v)
{
    extern __shared__ char smem[];
    const uint32_t uAs = smem_u32(smem);              // A stages
    const uint32_t uBs = uAs + STAGES * STAGEB;       // B stages

    const int tid  = threadIdx.x;
    const int lane = tid & 31;
    const int warp = tid >> 5;
    const int wm   = warp >> 1;     // 0..3 (M, 32 rows)
    const int wn   = warp & 1;      // 0..1 (N, 64 cols)
    const int gid  = lane >> 2;
    const int tig  = lane & 3;

    const int nx   = blockIdx.x;
    const int m0   = blockIdx.y * BM;
    const int n0   = nx * BN;
    const int bidx = m0 >> 11;

    float acc[2][8][4];
    #pragma unroll
    for (int i = 0; i < 2; i++)
        #pragma unroll
        for (int j = 0; j < 8; j++)
            #pragma unroll
            for (int k = 0; k < 4; k++) acc[i][j][k] = 0.f;

    // cp.async mapping (256 threads): A/B each 128 rows x 8 16B-chunks = 1024
    // ops -> rows {ra+32j} j=0..3, chunk c8.
    const int ra = tid >> 3;            // 0..31
    const int c8 = tid & 7;             // 0..7
    const uint32_t dA = uAs + (uint32_t)ra * 144 + (uint32_t)c8 * 16;
    const uint32_t dB = uBs + (uint32_t)ra * 144 + (uint32_t)c8 * 16;
    const __nv_bfloat16* pA = g_encb + (size_t)(m0 + ra) * DDIM + c8 * 8;
    const __nv_bfloat16* pB = g_w2b  + (size_t)(n0 + ra) * DDIM + c8 * 8;

    #define ISSUE_TILE(c, s)                                                     \
    do {                                                                         \
        const uint32_t _so = (uint32_t)(s) * STAGEB;                             \
        const __nv_bfloat16* _ga = pA + (size_t)(c) * BK;                        \
        const __nv_bfloat16* _gb = pB + (size_t)(c) * BK;                        \
        _Pragma("unroll")                                                        \
        for (int j = 0; j < 4; j++) {                                            \
            cp16(dA + _so + (uint32_t)j * 4608u, _ga + (size_t)j * 32 * DDIM);   \
            cp16(dB + _so + (uint32_t)j * 4608u, _gb + (size_t)j * 32 * DDIM);   \
        }                                                                        \
        asm volatile("cp.async.commit_group;");                                  \
    } while (0)

    // ldmatrix base addresses (lane-dependent)
    const uint32_t aBase = uAs + (uint32_t)(wm * 32 + (lane & 15)) * 144 + (uint32_t)(lane >> 4) * 16;
    const uint32_t bBase = uBs + (uint32_t)(wn * 64 + (lane & 15)) * 144 + (uint32_t)(lane >> 4) * 16;

    uint32_t fa[2][4];
    uint32_t fb[4][4];

    // B issued first (latency cover before the first mma of COMP).
    #define LOADF(s, ks)                                                         \
    do {                                                                         \
        const uint32_t _o = (uint32_t)(s) * STAGEB + (uint32_t)(ks) * 32u;       \
        _Pragma("unroll")                                                        \
        for (int q = 0; q < 4; q++)                                              \
            LDSM4(fb[q][0], fb[q][1], fb[q][2], fb[q][3],                        \
                  bBase + _o + (uint32_t)q * 2304u);                             \
        _Pragma("unroll")                                                        \
        for (int mi = 0; mi < 2; mi++)                                           \
            LDSM4(fa[mi][0], fa[mi][1], fa[mi][2], fa[mi][3],                    \
                  aBase + _o + (uint32_t)mi * 2304u);                            \
    } while (0)

    // fb x4 pair q covers ni=2q (regs 0,2) and ni=2q+1 (regs 1,3)
    #define COMP()                                                               \
    do {                                                                         \
        _Pragma("unroll")                                                        \
        for (int mi = 0; mi < 2; mi++)                                           \
            _Pragma("unroll")                                                    \
            for (int ni = 0; ni < 8; ni++)                                       \
                mma_bf16(acc[mi][ni], fa[mi],                                    \
                         fb[ni >> 1][ni & 1], fb[ni >> 1][2 + (ni & 1)]);        \
    } while (0)

    // Prologue: fill stages 0 and 1; stage 0 resident before first frag load.
    ISSUE_TILE(0, 0);
    ISSUE_TILE(1, 1);
    asm volatile("cp.async.wait_group 1;");
    __syncthreads();

    for (int kt = 0; kt < KT; kt++) {
        const int s = kt % STAGES;
        LOADF(s, 0);
        if (kt + 2 < KT) ISSUE_TILE(kt + 2, (kt + 2) % STAGES);
        COMP();
        LOADF(s, 1); COMP();
        LOADF(s, 2); COMP();
        LOADF(s, 3); COMP();
        if (kt + 1 < KT) {
            if (kt + 2 < KT) asm volatile("cp.async.wait_group 1;");
            else             asm volatile("cp.async.wait_group 0;");
            __syncthreads();
        }
    }

    // Epilogue: relu(acc + qh) * v, reduced over this CTA's 128 d-columns.
    float* partial = (float*)(smem + SMEM_PART);   // [2][128]
    float pr[2][2];
    #pragma unroll
    for (int mi = 0; mi < 2; mi++) { pr[mi][0] = 0.f; pr[mi][1] = 0.f; }

    #pragma unroll
    for (int ni = 0; ni < 8; ni++) {
        const int c = n0 + wn * 64 + ni * 8 + tig * 2;
        const float q0 = g_qh[(size_t)bidx * DDIM + c];
        const float q1 = g_qh[(size_t)bidx * DDIM + c + 1];
        const float v0 = v[c];
        const float v1 = v[c + 1];
        #pragma unroll
        for (int mi = 0; mi < 2; mi++) {
            pr[mi][0] += fmaxf(acc[mi][ni][0] + q0, 0.f) * v0;
            pr[mi][0] += fmaxf(acc[mi][ni][1] + q1, 0.f) * v1;
            pr[mi][1] += fmaxf(acc[mi][ni][2] + q0, 0.f) * v0;
            pr[mi][1] += fmaxf(acc[mi][ni][3] + q1, 0.f) * v1;
        }
    }

    __syncthreads();
    #pragma unroll
    for (int mi = 0; mi < 2; mi++)
        #pragma unroll
        for (int j = 0; j < 2; j++) {
            float p = pr[mi][j];
            p += __shfl_xor_sync(0xFFFFFFFFu, p, 1);
            p += __shfl_xor_sync(0xFFFFFFFFu, p, 2);
            if (tig == 0) partial[wn * BM + wm * 32 + mi * 16 + j * 8 + gid] = p;
        }
    __syncthreads();

    if (tid < BM) {
        const float s = partial[tid] + partial[BM + tid];
        g_part[(size_t)nx * MTOT + m0 + tid] = s;
    }
}

// ---------------------------------------------------------------------------
// Sum 8 N-strip partials -> scores, softmax over T. 1024 threads (2 t each).
__global__ __launch_bounds__(1024) void softmax_kernel(float* __restrict__ out)
{
    const int b = blockIdx.x;
    const int tid = threadIdx.x;
    __shared__ float red[1024];

    float vals[2];
    #pragma unroll
    for (int j = 0; j < 2; j++) {
        const int t = tid + j * 1024;
        float s = 0.f;
        #pragma unroll
        for (int nxi = 0; nxi < NTILES; nxi++)
            s += g_part[(size_t)nxi * MTOT + (size_t)b * TDIM + t];
        vals[j] = s;
    }
    float mx = fmaxf(vals[0], vals[1]);

    red[tid] = mx;
    __syncthreads();
    #pragma unroll
    for (int o = 512; o > 0; o >>= 1) {
        if (tid < o) red[tid] = fmaxf(red[tid], red[tid + o]);
        __syncthreads();
    }
    const float m = red[0];
    __syncthreads();

    float sum = 0.f;
    #pragma unroll
    for (int j = 0; j < 2; j++) {
        vals[j] = expf(vals[j] - m);
        sum += vals[j];
    }
    red[tid] = sum;
    __syncthreads();
    #pragma unroll
    for (int o = 512; o > 0; o >>= 1) {
        if (tid < o) red[tid] += red[tid + o];
        __syncthreads();
    }
    const float inv = 1.f / red[0];

    #pragma unroll
    for (int j = 0; j < 2; j++)
        out[(size_t)b * TDIM + tid + j * 1024] = vals[j] * inv;
}

// ---------------------------------------------------------------------------
extern "C" void kernel_launch(void* const* d_in, const int* in_sizes, int n_in,
                              void* d_out, int out_size)
{
    const float* hidden = (const float*)d_in[0];
    const float* enc    = (const float*)d_in[1];
    const float* W      = (const float*)d_in[2];
    const float* bias   = (const float*)d_in[3];
    const float* v      = (const float*)d_in[4];
    float* out = (float*)d_out;

    cudaFuncSetAttribute(bf_gemm, cudaFuncAttributeMaxDynamicSharedMemorySize, SMEM_TOTAL);

    conv_enc<<<65536, 256>>>((const float4*)enc);
    conv_w2<<<DDIM, 256>>>(W);
    qh_kernel<<<dim3(DDIM / 8, BDIM), 256>>>(hidden, W, bias);
    bf_gemm<<<dim3(NTILES, MTOT / BM), 256, SMEM_TOTAL>>>(v);
    softmax_kernel<<<BDIM, 1024>>>(out);
}

// round 16
// speedup vs baseline: 1.3951x; 1.0381x over previous
#include <cuda_runtime.h>
#include <cuda_bf16.h>
#include <math.h>
#include <stdint.h>

// Problem constants
#define DDIM 1024
#define TDIM 2048
#define BDIM 32
#define MTOT 65536
#define WSTRIDE 2048        // W row stride in floats (2*D)

// GEMM tiling (bf16): 128x128 CTA tile, 8 warps of 32x64 warp tiles, 2 CTAs/SM
#define BM 128
#define BN 128
#define BK 64               // bf16 k-elements per stage
#define NTILES 8            // 1024 / BN
#define KT 16               // 1024 / BK
#define STAGES 3

#define STAGEB 18432u       // bytes per stage per matrix: 128 rows * 144B
#define SMEM_PART 110592u   // after 3*(A+B) stages
#define SMEM_TOTAL 111616u  // + partial[2][128] floats

// Scratch (static __device__ arrays: allocation-free)
__device__ __nv_bfloat16 g_encb[(size_t)MTOT * DDIM];
__device__ __nv_bfloat16 g_w2b[(size_t)DDIM * DDIM];
__device__ float g_qh[BDIM * DDIM];
__device__ float g_part[(size_t)NTILES * MTOT];

// ---------------------------------------------------------------------------
__device__ __forceinline__ void mma_bf16(float* d, const uint32_t* a, uint32_t b0, uint32_t b1) {
    asm volatile(
        "mma.sync.aligned.m16n8k16.row.col.f32.bf16.bf16.f32 "
        "{%0,%1,%2,%3}, {%4,%5,%6,%7}, {%8,%9}, {%0,%1,%2,%3};"
        : "+f"(d[0]), "+f"(d[1]), "+f"(d[2]), "+f"(d[3])
        : "r"(a[0]), "r"(a[1]), "r"(a[2]), "r"(a[3]), "r"(b0), "r"(b1));
}
__device__ __forceinline__ void cp16(uint32_t dst, const void* src) {
    asm volatile("cp.async.cg.shared.global [%0], [%1], 16;" :: "r"(dst), "l"(src));
}
#define LDSM4(r0, r1, r2, r3, addr) \
    asm volatile("ldmatrix.sync.aligned.m8n8.x4.shared.b16 {%0,%1,%2,%3}, [%4];" \
        : "=r"(r0), "=r"(r1), "=r"(r2), "=r"(r3) : "r"(addr))

__device__ __forceinline__ uint32_t smem_u32(const void* p) {
    uint32_t a;
    asm("{ .reg .u64 t; cvta.to.shared.u64 t, %1; cvt.u32.u64 %0, t; }" : "=r"(a) : "l"(p));
    return a;
}

// ---------------------------------------------------------------------------
// Convert enc (f32) -> g_encb (bf16). One float4 per thread.
__global__ __launch_bounds__(256) void conv_enc(const float4* __restrict__ src)
{
    const size_t i = (size_t)blockIdx.x * 256 + threadIdx.x;
    const float4 x = src[i];
    __nv_bfloat162 p0 = __floats2bfloat162_rn(x.x, x.y);
    __nv_bfloat162 p1 = __floats2bfloat162_rn(x.z, x.w);
    uint2 o;
    o.x = *(uint32_t*)&p0;
    o.y = *(uint32_t*)&p1;
    ((uint2*)g_encb)[i] = o;
}

// Convert W2 = W[:, 1024:2048] -> g_w2b (bf16).
__global__ __launch_bounds__(256) void conv_w2(const float* __restrict__ W)
{
    const int n = blockIdx.x;
    const int t = threadIdx.x;
    const float4 x = *(const float4*)(W + (size_t)n * WSTRIDE + DDIM + t * 4);
    __nv_bfloat162 p0 = __floats2bfloat162_rn(x.x, x.y);
    __nv_bfloat162 p1 = __floats2bfloat162_rn(x.z, x.w);
    uint2 o;
    o.x = *(uint32_t*)&p0;
    o.y = *(uint32_t*)&p1;
    ((uint2*)(g_w2b + (size_t)n * DDIM))[t] = o;
}

// ---------------------------------------------------------------------------
// qh[b,d] = W1[d,:] . hidden[b,:] + bias[d]   (proven R10 version)
__global__ __launch_bounds__(256) void qh_kernel(
    const float* __restrict__ hidden, const float* __restrict__ W,
    const float* __restrict__ bias)
{
    const int b = blockIdx.y;
    const int warp = threadIdx.x >> 5;
    const int lane = threadIdx.x & 31;
    const int d = blockIdx.x * 8 + warp;

    const float* wr = W + (size_t)d * WSTRIDE;
    const float* h  = hidden + (size_t)b * DDIM;

    float acc = 0.f;
    #pragma unroll 8
    for (int k = lane; k < DDIM; k += 32) acc += wr[k] * h[k];
    #pragma unroll
    for (int o = 16; o > 0; o >>= 1) acc += __shfl_xor_sync(0xFFFFFFFFu, acc, o);
    if (lane == 0) g_qh[(size_t)b * DDIM + d] = acc + bias[d];
}

// ---------------------------------------------------------------------------
// bf16 GEMM: 128x128 CTA tile, 256 threads (8 warps, 32x64 warp tiles),
// 2 CTAs/SM, 3-stage cp.async pipeline. Split-COMP rotation: COMP03 frees
// fb01 before its reload, COMP47 frees fb23+fa — per-ks LDSM latency hidden
// under HMMAs with ZERO extra fragment registers.
__global__ __launch_bounds__(256, 2) void bf_gemm(const float* __restrict__ v)
{
    extern __shared__ char smem[];
    const uint32_t uAs = smem_u32(smem);              // A stages
    const uint32_t uBs = uAs + STAGES * STAGEB;       // B stages

    const int tid  = threadIdx.x;
    const int lane = tid & 31;
    const int warp = tid >> 5;
    const int wm   = warp >> 1;     // 0..3 (M, 32 rows)
    const int wn   = warp & 1;      // 0..1 (N, 64 cols)
    const int gid  = lane >> 2;
    const int tig  = lane & 3;

    const int nx   = blockIdx.x;
    const int m0   = blockIdx.y * BM;
    const int n0   = nx * BN;
    const int bidx = m0 >> 11;

    float acc[2][8][4];
    #pragma unroll
    for (int i = 0; i < 2; i++)
        #pragma unroll
        for (int j = 0; j < 8; j++)
            #pragma unroll
            for (int k = 0; k < 4; k++) acc[i][j][k] = 0.f;

    // cp.async mapping (256 threads): A/B each 128 rows x 8 16B-chunks = 1024
    // ops -> rows {ra+32j} j=0..3, chunk c8.
    const int ra = tid >> 3;            // 0..31
    const int c8 = tid & 7;             // 0..7
    const uint32_t dA = uAs + (uint32_t)ra * 144 + (uint32_t)c8 * 16;
    const uint32_t dB = uBs + (uint32_t)ra * 144 + (uint32_t)c8 * 16;
    const __nv_bfloat16* pA = g_encb + (size_t)(m0 + ra) * DDIM + c8 * 8;
    const __nv_bfloat16* pB = g_w2b  + (size_t)(n0 + ra) * DDIM + c8 * 8;

    #define ISSUE_TILE(c, soff)                                                  \
    do {                                                                         \
        const __nv_bfloat16* _ga = pA + (size_t)(c) * BK;                        \
        const __nv_bfloat16* _gb = pB + (size_t)(c) * BK;                        \
        _Pragma("unroll")                                                        \
        for (int j = 0; j < 4; j++) {                                            \
            cp16(dA + (soff) + (uint32_t)j * 4608u, _ga + (size_t)j * 32 * DDIM);\
            cp16(dB + (soff) + (uint32_t)j * 4608u, _gb + (size_t)j * 32 * DDIM);\
        }                                                                        \
        asm volatile("cp.async.commit_group;");                                  \
    } while (0)

    // ldmatrix base addresses (lane-dependent)
    const uint32_t aBase = uAs + (uint32_t)(wm * 32 + (lane & 15)) * 144 + (uint32_t)(lane >> 4) * 16;
    const uint32_t bBase = uBs + (uint32_t)(wn * 64 + (lane & 15)) * 144 + (uint32_t)(lane >> 4) * 16;

    uint32_t fa[2][4];
    uint32_t fb[4][4];

    #define LDSM_FB01(off)                                                       \
    do {                                                                         \
        LDSM4(fb[0][0], fb[0][1], fb[0][2], fb[0][3], bBase + (off));            \
        LDSM4(fb[1][0], fb[1][1], fb[1][2], fb[1][3], bBase + (off) + 2304u);    \
    } while (0)
    #define LDSM_FB23(off)                                                       \
    do {                                                                         \
        LDSM4(fb[2][0], fb[2][1], fb[2][2], fb[2][3], bBase + (off) + 4608u);    \
        LDSM4(fb[3][0], fb[3][1], fb[3][2], fb[3][3], bBase + (off) + 6912u);    \
    } while (0)
    #define LDSM_FA(off)                                                         \
    do {                                                                         \
        LDSM4(fa[0][0], fa[0][1], fa[0][2], fa[0][3], aBase + (off));            \
        LDSM4(fa[1][0], fa[1][1], fa[1][2], fa[1][3], aBase + (off) + 2304u);    \
    } while (0)

    // COMP split: ni 0-3 uses fb[0..1], ni 4-7 uses fb[2..3]; both use fa.
    #define COMP03()                                                             \
    do {                                                                         \
        _Pragma("unroll")                                                        \
        for (int mi = 0; mi < 2; mi++)                                           \
            _Pragma("unroll")                                                    \
            for (int ni = 0; ni < 4; ni++)                                       \
                mma_bf16(acc[mi][ni], fa[mi],                                    \
                         fb[ni >> 1][ni & 1], fb[ni >> 1][2 + (ni & 1)]);        \
    } while (0)
    #define COMP47()                                                             \
    do {                                                                         \
        _Pragma("unroll")                                                        \
        for (int mi = 0; mi < 2; mi++)                                           \
            _Pragma("unroll")                                                    \
            for (int ni = 4; ni < 8; ni++)                                       \
                mma_bf16(acc[mi][ni], fa[mi],                                    \
                         fb[ni >> 1][ni & 1], fb[ni >> 1][2 + (ni & 1)]);        \
    } while (0)

    // Prologue: fill stages 0 and 1; stage 0 resident, load ks0 fragments.
    ISSUE_TILE(0, 0u);
    ISSUE_TILE(1, STAGEB);
    asm volatile("cp.async.wait_group 1;");
    __syncthreads();
    LDSM_FB01(0u); LDSM_FB23(0u); LDSM_FA(0u);

    uint32_t sOff   = 0u;                 // stage offset being consumed
    uint32_t issOff = 2u * STAGEB;        // stage offset for tile kt+2

    for (int kt = 0; kt < KT; kt++) {
        // ks0 (fragments already resident); reload for ks1 interleaved
        COMP03(); LDSM_FB01(sOff + 32u);
        if (kt + 2 < KT) ISSUE_TILE(kt + 2, issOff);
        COMP47(); LDSM_FB23(sOff + 32u); LDSM_FA(sOff + 32u);
        // ks1
        COMP03(); LDSM_FB01(sOff + 64u);
        COMP47(); LDSM_FB23(sOff + 64u); LDSM_FA(sOff + 64u);
        // ks2
        COMP03(); LDSM_FB01(sOff + 96u);
        COMP47(); LDSM_FB23(sOff + 96u); LDSM_FA(sOff + 96u);
        // ks3 (no reload within stage)
        COMP03(); COMP47();

        if (kt + 1 < KT) {
            if (kt + 2 < KT) asm volatile("cp.async.wait_group 1;");
            else             asm volatile("cp.async.wait_group 0;");
            __syncthreads();
            sOff   += STAGEB; if (sOff   == 3u * STAGEB) sOff   = 0u;
            issOff += STAGEB; if (issOff == 3u * STAGEB) issOff = 0u;
            LDSM_FB01(sOff); LDSM_FB23(sOff); LDSM_FA(sOff);
        }
    }

    // Epilogue: relu(acc + qh) * v, reduced over this CTA's 128 d-columns.
    float* partial = (float*)(smem + SMEM_PART);   // [2][128]
    float pr[2][2];
    #pragma unroll
    for (int mi = 0; mi < 2; mi++) { pr[mi][0] = 0.f; pr[mi][1] = 0.f; }

    #pragma unroll
    for (int ni = 0; ni < 8; ni++) {
        const int c = n0 + wn * 64 + ni * 8 + tig * 2;
        const float q0 = g_qh[(size_t)bidx * DDIM + c];
        const float q1 = g_qh[(size_t)bidx * DDIM + c + 1];
        const float v0 = v[c];
        const float v1 = v[c + 1];
        #pragma unroll
        for (int mi = 0; mi < 2; mi++) {
            pr[mi][0] += fmaxf(acc[mi][ni][0] + q0, 0.f) * v0;
            pr[mi][0] += fmaxf(acc[mi][ni][1] + q1, 0.f) * v1;
            pr[mi][1] += fmaxf(acc[mi][ni][2] + q0, 0.f) * v0;
            pr[mi][1] += fmaxf(acc[mi][ni][3] + q1, 0.f) * v1;
        }
    }

    __syncthreads();
    #pragma unroll
    for (int mi = 0; mi < 2; mi++)
        #pragma unroll
        for (int j = 0; j < 2; j++) {
            float p = pr[mi][j];
            p += __shfl_xor_sync(0xFFFFFFFFu, p, 1);
            p += __shfl_xor_sync(0xFFFFFFFFu, p, 2);
            if (tig == 0) partial[wn * BM + wm * 32 + mi * 16 + j * 8 + gid] = p;
        }
    __syncthreads();

    if (tid < BM) {
        const float s = partial[tid] + partial[BM + tid];
        g_part[(size_t)nx * MTOT + m0 + tid] = s;
    }
}

// ---------------------------------------------------------------------------
// Sum 8 N-strip partials -> scores, softmax over T. 1024 threads (2 t each).
__global__ __launch_bounds__(1024) void softmax_kernel(float* __restrict__ out)
{
    const int b = blockIdx.x;
    const int tid = threadIdx.x;
    __shared__ float red[1024];

    float vals[2];
    #pragma unroll
    for (int j = 0; j < 2; j++) {
        const int t = tid + j * 1024;
        float s = 0.f;
        #pragma unroll
        for (int nxi = 0; nxi < NTILES; nxi++)
            s += g_part[(size_t)nxi * MTOT + (size_t)b * TDIM + t];
        vals[j] = s;
    }
    float mx = fmaxf(vals[0], vals[1]);

    red[tid] = mx;
    __syncthreads();
    #pragma unroll
    for (int o = 512; o > 0; o >>= 1) {
        if (tid < o) red[tid] = fmaxf(red[tid], red[tid + o]);
        __syncthreads();
    }
    const float m = red[0];
    __syncthreads();

    float sum = 0.f;
    #pragma unroll
    for (int j = 0; j < 2; j++) {
        vals[j] = expf(vals[j] - m);
        sum += vals[j];
    }
    red[tid] = sum;
    __syncthreads();
    #pragma unroll
    for (int o = 512; o > 0; o >>= 1) {
        if (tid < o) red[tid] += red[tid + o];
        __syncthreads();
    }
    const float inv = 1.f / red[0];

    #pragma unroll
    for (int j = 0; j < 2; j++)
        out[(size_t)b * TDIM + tid + j * 1024] = vals[j] * inv;
}

// ---------------------------------------------------------------------------
extern "C" void kernel_launch(void* const* d_in, const int* in_sizes, int n_in,
                              void* d_out, int out_size)
{
    const float* hidden = (const float*)d_in[0];
    const float* enc    = (const float*)d_in[1];
    const float* W      = (const float*)d_in[2];
    const float* bias   = (const float*)d_in[3];
    const float* v      = (const float*)d_in[4];
    float* out = (float*)d_out;

    cudaFuncSetAttribute(bf_gemm, cudaFuncAttributeMaxDynamicSharedMemorySize, SMEM_TOTAL);

    conv_enc<<<65536, 256>>>((const float4*)enc);
    conv_w2<<<DDIM, 256>>>(W);
    qh_kernel<<<dim3(DDIM / 8, BDIM), 256>>>(hidden, W, bias);
    bf_gemm<<<dim3(NTILES, MTOT / BM), 256, SMEM_TOTAL>>>(v);
    softmax_kernel<<<BDIM, 1024>>>(out);
}